// round 1
// baseline (speedup 1.0000x reference)
#include <cuda_runtime.h>
#include <math.h>

#define BBATCH 16
#define NPTS   4096
#define THREADS 256
#define ROWS_PER_THREAD 2
#define ROWS_PER_BLOCK (THREADS * ROWS_PER_THREAD)   // 512
#define TILES (NPTS / ROWS_PER_BLOCK)                // 8
#define NBLOCKS (TILES * BBATCH * 2)                 // 256
#define EPSF 1e-12f

// Per-block partial sums (deterministic 2-stage reduction, no float atomics).
__device__ float g_partials[NBLOCKS];

// One direction per blockIdx.z:
//   z==0: queries = keypoints1 rows (forward),  targets = keypoints2
//   z==1: queries = keypoints2 rows (backward), targets = keypoints1
__global__ __launch_bounds__(THREADS)
void chamfer_dir_kernel(const float* __restrict__ kp1,
                        const float* __restrict__ kp2,
                        const float* __restrict__ sig1,
                        const float* __restrict__ sig2)
{
    const float *qk, *tk, *qs, *ts;
    if (blockIdx.z == 0) { qk = kp1; tk = kp2; qs = sig1; ts = sig2; }
    else                 { qk = kp2; tk = kp1; qs = sig2; ts = sig1; }

    const int b = blockIdx.y;

    extern __shared__ float4 st[];   // NPTS float4 = 64 KB: {x, y, z, x^2+y^2+z^2}

    // Cooperative load of the target set for this batch (coalesced per plane).
    {
        const float* tp = tk + (size_t)b * 3 * NPTS;
        for (int i = threadIdx.x; i < NPTS; i += THREADS) {
            float x = tp[i];
            float y = tp[NPTS + i];
            float z = tp[2 * NPTS + i];
            st[i] = make_float4(x, y, z, fmaf(x, x, fmaf(y, y, z * z)));
        }
    }
    __syncthreads();

    // Each thread owns ROWS_PER_THREAD query rows.
    const float* qp = qk + (size_t)b * 3 * NPTS;
    int   m[ROWS_PER_THREAD];
    float a0x[ROWS_PER_THREAD], a0y[ROWS_PER_THREAD], a0z[ROWS_PER_THREAD];
    float sqa[ROWS_PER_THREAD];
    float best[ROWS_PER_THREAD];
    int   bidx[ROWS_PER_THREAD];

    #pragma unroll
    for (int r = 0; r < ROWS_PER_THREAD; r++) {
        m[r] = blockIdx.x * ROWS_PER_BLOCK + r * THREADS + threadIdx.x;
        float ax = qp[m[r]];
        float ay = qp[NPTS + m[r]];
        float az = qp[2 * NPTS + m[r]];
        a0x[r] = -2.0f * ax;
        a0y[r] = -2.0f * ay;
        a0z[r] = -2.0f * az;
        sqa[r] = fmaf(ax, ax, fmaf(ay, ay, az * az));
        best[r] = __int_as_float(0x7f800000);  // +inf
        bidx[r] = 0;
    }

    // Main loop: v = ||b||^2 - 2 a.b  (== d^2 - ||a||^2, same argmin as d^2).
    #pragma unroll 8
    for (int n = 0; n < NPTS; n++) {
        float4 p = st[n];
        #pragma unroll
        for (int r = 0; r < ROWS_PER_THREAD; r++) {
            float v = fmaf(a0x[r], p.x, fmaf(a0y[r], p.y, fmaf(a0z[r], p.z, p.w)));
            bidx[r] = (v < best[r]) ? n : bidx[r];   // strict < keeps first (jnp.argmin)
            best[r] = fminf(best[r], v);
        }
    }

    // Per-thread loss contributions.
    float acc = 0.0f;
    #pragma unroll
    for (int r = 0; r < ROWS_PER_THREAD; r++) {
        float d2   = best[r] + sqa[r];
        float mind = sqrtf(fmaxf(d2, EPSF));
        float sg   = 0.5f * (qs[(size_t)b * NPTS + m[r]] + ts[(size_t)b * NPTS + bidx[r]]);
        acc += logf(sg) + mind / sg;
    }

    // Block-level tree reduction.
    __shared__ float red[THREADS];
    red[threadIdx.x] = acc;
    __syncthreads();
    #pragma unroll
    for (int s = THREADS / 2; s > 32; s >>= 1) {
        if (threadIdx.x < s) red[threadIdx.x] += red[threadIdx.x + s];
        __syncthreads();
    }
    if (threadIdx.x < 32) {
        float v = red[threadIdx.x] + red[threadIdx.x + 32];
        #pragma unroll
        for (int o = 16; o > 0; o >>= 1)
            v += __shfl_down_sync(0xffffffffu, v, o);
        if (threadIdx.x == 0) {
            int bid = blockIdx.z * (BBATCH * TILES) + blockIdx.y * TILES + blockIdx.x;
            g_partials[bid] = v;
        }
    }
}

__global__ __launch_bounds__(NBLOCKS)
void chamfer_final_kernel(float* __restrict__ out)
{
    __shared__ double red[NBLOCKS];
    red[threadIdx.x] = (double)g_partials[threadIdx.x];
    __syncthreads();
    for (int s = NBLOCKS / 2; s > 0; s >>= 1) {
        if (threadIdx.x < s) red[threadIdx.x] += red[threadIdx.x + s];
        __syncthreads();
    }
    if (threadIdx.x == 0) {
        // forward mean over B*M plus backward mean over B*N, M == N == 4096
        out[0] = (float)(red[0] * (1.0 / ((double)BBATCH * (double)NPTS)));
    }
}

extern "C" void kernel_launch(void* const* d_in, const int* in_sizes, int n_in,
                              void* d_out, int out_size)
{
    (void)in_sizes; (void)n_in; (void)out_size;
    const float* kp1  = (const float*)d_in[0];  // [B, 3, M]
    const float* kp2  = (const float*)d_in[1];  // [B, 3, N]
    const float* sig1 = (const float*)d_in[2];  // [B, M]
    const float* sig2 = (const float*)d_in[3];  // [B, N]
    float* out = (float*)d_out;

    static_assert(sizeof(float4) * NPTS == 65536, "smem size");
    cudaFuncSetAttribute(chamfer_dir_kernel,
                         cudaFuncAttributeMaxDynamicSharedMemorySize, 65536);

    dim3 grid(TILES, BBATCH, 2);
    chamfer_dir_kernel<<<grid, THREADS, 65536>>>(kp1, kp2, sig1, sig2);
    chamfer_final_kernel<<<1, NBLOCKS>>>(out);
}

// round 2
// speedup vs baseline: 1.2021x; 1.2021x over previous
#include <cuda_runtime.h>
#include <math.h>
#include <stdint.h>

#define BBATCH 16
#define NPTS   4096
#define THREADS 256
#define RPT 2
#define ROWS_PER_BLOCK (THREADS * RPT)     // 512
#define TILES (NPTS / ROWS_PER_BLOCK)      // 8
#define NBLOCKS (TILES * BBATCH * 2)       // 256
#define GSIZE 64
#define NGROUPS (NPTS / GSIZE)             // 64
#define EPSF 1e-12f

__device__ float g_partials[NBLOCKS];

__device__ __forceinline__ uint64_t pack2(float lo, float hi) {
    uint64_t r;
    asm("mov.b64 %0, {%1,%2};" : "=l"(r) : "f"(lo), "f"(hi));
    return r;
}
__device__ __forceinline__ void unpack2(uint64_t v, float& lo, float& hi) {
    asm("mov.b64 {%0,%1}, %2;" : "=f"(lo), "=f"(hi) : "l"(v));
}
// Packed 2xfp32 FMA (Blackwell f32x2 path; per-lane IEEE fma.rn.f32)
__device__ __forceinline__ uint64_t fma2(uint64_t a, uint64_t b, uint64_t c) {
    uint64_t d;
    asm("fma.rn.f32x2 %0, %1, %2, %3;" : "=l"(d) : "l"(a), "l"(b), "l"(c));
    return d;
}

// One direction per blockIdx.z:
//   z==0: queries = keypoints1 (forward),  targets = keypoints2
//   z==1: queries = keypoints2 (backward), targets = keypoints1
__global__ __launch_bounds__(THREADS)
void chamfer_dir_kernel(const float* __restrict__ kp1,
                        const float* __restrict__ kp2,
                        const float* __restrict__ sig1,
                        const float* __restrict__ sig2)
{
    const float *qk, *tk, *qs, *ts;
    if (blockIdx.z == 0) { qk = kp1; tk = kp2; qs = sig1; ts = sig2; }
    else                 { qk = kp2; tk = kp1; qs = sig2; ts = sig1; }

    const int b = blockIdx.y;

    // SoA target tile: x, y, z, ||p||^2 — packed pairs come free from LDS.128
    extern __shared__ float sm[];
    float* sx = sm;
    float* sy = sm + NPTS;
    float* sz = sm + 2 * NPTS;
    float* sw = sm + 3 * NPTS;

    {
        const float* tp = tk + (size_t)b * 3 * NPTS;
        for (int i = threadIdx.x; i < NPTS; i += THREADS) {
            float x = tp[i];
            float y = tp[NPTS + i];
            float z = tp[2 * NPTS + i];
            sx[i] = x; sy[i] = y; sz[i] = z;
            sw[i] = fmaf(x, x, fmaf(y, y, z * z));
        }
    }
    __syncthreads();

    const float* qp = qk + (size_t)b * 3 * NPTS;
    int      m[RPT];
    float    a0x[RPT], a0y[RPT], a0z[RPT], sqa[RPT];
    uint64_t ax2[RPT], ay2[RPT], az2[RPT];
    float    best[RPT];
    int      bg[RPT];

    #pragma unroll
    for (int r = 0; r < RPT; r++) {
        m[r] = blockIdx.x * ROWS_PER_BLOCK + r * THREADS + threadIdx.x;
        float x = qp[m[r]];
        float y = qp[NPTS + m[r]];
        float z = qp[2 * NPTS + m[r]];
        a0x[r] = -2.0f * x;  a0y[r] = -2.0f * y;  a0z[r] = -2.0f * z;
        ax2[r] = pack2(a0x[r], a0x[r]);
        ay2[r] = pack2(a0y[r], a0y[r]);
        az2[r] = pack2(a0z[r], a0z[r]);
        sqa[r] = fmaf(x, x, fmaf(y, y, z * z));
        best[r] = __int_as_float(0x7f800000);   // +inf
        bg[r] = 0;
    }

    // Main loop: v = ||p||^2 - 2 a.p  (same argmin as d^2). Group-min only —
    // index recovered by replaying the winning 64-element group afterwards.
    for (int g = 0; g < NGROUPS; g++) {
        float gm[RPT];
        #pragma unroll
        for (int r = 0; r < RPT; r++) gm[r] = __int_as_float(0x7f800000);

        const int base = g * GSIZE;
        #pragma unroll 4
        for (int k = 0; k < GSIZE; k += 4) {
            const int n = base + k;
            ulonglong2 X = *(const ulonglong2*)(sx + n);  // (x[n],x[n+1]),(x[n+2],x[n+3])
            ulonglong2 Y = *(const ulonglong2*)(sy + n);
            ulonglong2 Z = *(const ulonglong2*)(sz + n);
            ulonglong2 W = *(const ulonglong2*)(sw + n);
            #pragma unroll
            for (int r = 0; r < RPT; r++) {
                uint64_t va = fma2(ax2[r], X.x, fma2(ay2[r], Y.x, fma2(az2[r], Z.x, W.x)));
                uint64_t vb = fma2(ax2[r], X.y, fma2(ay2[r], Y.y, fma2(az2[r], Z.y, W.y)));
                float l0, h0, l1, h1;
                unpack2(va, l0, h0);
                unpack2(vb, l1, h1);
                gm[r] = fminf(gm[r], fminf(fminf(l0, h0), fminf(l1, h1)));
            }
        }
        #pragma unroll
        for (int r = 0; r < RPT; r++) {
            bg[r]   = (gm[r] < best[r]) ? g : bg[r];   // strict < keeps earliest group
            best[r] = fminf(best[r], gm[r]);
        }
    }

    // Replay winning group per row: first-argmin within it (exact same FMA chain).
    float acc = 0.0f;
    #pragma unroll
    for (int r = 0; r < RPT; r++) {
        const int base = bg[r] * GSIZE;
        float lb = __int_as_float(0x7f800000);
        int   bi = base;
        for (int k = 0; k < GSIZE; k++) {
            const int n = base + k;
            float v = fmaf(a0x[r], sx[n], fmaf(a0y[r], sy[n], fmaf(a0z[r], sz[n], sw[n])));
            bi = (v < lb) ? n : bi;                     // strict < keeps first index
            lb = fminf(lb, v);
        }
        float d2   = best[r] + sqa[r];
        float mind = sqrtf(fmaxf(d2, EPSF));
        float sg   = 0.5f * (qs[(size_t)b * NPTS + m[r]] + ts[(size_t)b * NPTS + bi]);
        acc += logf(sg) + mind / sg;
    }

    // Block reduction -> per-block partial.
    __shared__ float red[THREADS];
    red[threadIdx.x] = acc;
    __syncthreads();
    #pragma unroll
    for (int s = THREADS / 2; s > 32; s >>= 1) {
        if (threadIdx.x < s) red[threadIdx.x] += red[threadIdx.x + s];
        __syncthreads();
    }
    if (threadIdx.x < 32) {
        float v = red[threadIdx.x] + red[threadIdx.x + 32];
        #pragma unroll
        for (int o = 16; o > 0; o >>= 1)
            v += __shfl_down_sync(0xffffffffu, v, o);
        if (threadIdx.x == 0) {
            int bid = blockIdx.z * (BBATCH * TILES) + blockIdx.y * TILES + blockIdx.x;
            g_partials[bid] = v;
        }
    }
}

__global__ __launch_bounds__(NBLOCKS)
void chamfer_final_kernel(float* __restrict__ out)
{
    __shared__ double red[NBLOCKS];
    red[threadIdx.x] = (double)g_partials[threadIdx.x];
    __syncthreads();
    for (int s = NBLOCKS / 2; s > 0; s >>= 1) {
        if (threadIdx.x < s) red[threadIdx.x] += red[threadIdx.x + s];
        __syncthreads();
    }
    if (threadIdx.x == 0)
        out[0] = (float)(red[0] * (1.0 / ((double)BBATCH * (double)NPTS)));
}

extern "C" void kernel_launch(void* const* d_in, const int* in_sizes, int n_in,
                              void* d_out, int out_size)
{
    (void)in_sizes; (void)n_in; (void)out_size;
    const float* kp1  = (const float*)d_in[0];  // [B, 3, M]
    const float* kp2  = (const float*)d_in[1];  // [B, 3, N]
    const float* sig1 = (const float*)d_in[2];  // [B, M]
    const float* sig2 = (const float*)d_in[3];  // [B, N]
    float* out = (float*)d_out;

    cudaFuncSetAttribute(chamfer_dir_kernel,
                         cudaFuncAttributeMaxDynamicSharedMemorySize, 65536);

    dim3 grid(TILES, BBATCH, 2);
    chamfer_dir_kernel<<<grid, THREADS, 65536>>>(kp1, kp2, sig1, sig2);
    chamfer_final_kernel<<<1, NBLOCKS>>>(out);
}

// round 4
// speedup vs baseline: 1.2263x; 1.0201x over previous
#include <cuda_runtime.h>
#include <math.h>
#include <stdint.h>

#define BBATCH 16
#define NPTS   4096
#define THREADS 256
#define RPT 2
#define ROWS_PER_BLOCK (THREADS * RPT)     // 512
#define TILES (NPTS / ROWS_PER_BLOCK)      // 8
#define NBLOCKS (TILES * BBATCH * 2)       // 256
#define GSIZE 64
#define NGROUPS (NPTS / GSIZE)             // 64
#define EPSF 1e-12f

__device__ float g_partials[NBLOCKS];

__device__ __forceinline__ uint64_t pack2(float lo, float hi) {
    uint64_t r;
    asm("mov.b64 %0, {%1,%2};" : "=l"(r) : "f"(lo), "f"(hi));
    return r;
}
// Packed 2xfp32 FMA, result stays in b64 domain (register pair).
__device__ __forceinline__ uint64_t fma2(uint64_t a, uint64_t b, uint64_t c) {
    uint64_t d;
    asm("fma.rn.f32x2 %0, %1, %2, %3;" : "=l"(d) : "l"(a), "l"(b), "l"(c));
    return d;
}
// Final packed FMA of a chain: destination pair aliased straight to two
// scalar floats (mov.b64 {lo,hi} is register-pair renaming for ptxas).
__device__ __forceinline__ void fma2_last(float& lo, float& hi,
                                          uint64_t a, uint64_t b, uint64_t c) {
    asm("{\n\t.reg .b64 t;\n\tfma.rn.f32x2 t, %2, %3, %4;\n\tmov.b64 {%0,%1}, t;\n\t}"
        : "=f"(lo), "=f"(hi) : "l"(a), "l"(b), "l"(c));
}

// One direction per blockIdx.z:
//   z==0: queries = keypoints1 (forward),  targets = keypoints2
//   z==1: queries = keypoints2 (backward), targets = keypoints1
__global__ __launch_bounds__(THREADS)
void chamfer_dir_kernel(const float* __restrict__ kp1,
                        const float* __restrict__ kp2,
                        const float* __restrict__ sig1,
                        const float* __restrict__ sig2)
{
    const float *qk, *tk, *qs, *ts;
    if (blockIdx.z == 0) { qk = kp1; tk = kp2; qs = sig1; ts = sig2; }
    else                 { qk = kp2; tk = kp1; qs = sig2; ts = sig1; }

    const int b = blockIdx.y;

    // SoA target tile: x, y, z, ||p||^2 — packed pairs come free from LDS.128
    extern __shared__ float sm[];
    float* sx = sm;
    float* sy = sm + NPTS;
    float* sz = sm + 2 * NPTS;
    float* sw = sm + 3 * NPTS;

    {
        const float* tp = tk + (size_t)b * 3 * NPTS;
        for (int i = threadIdx.x; i < NPTS; i += THREADS) {
            float x = tp[i];
            float y = tp[NPTS + i];
            float z = tp[2 * NPTS + i];
            sx[i] = x; sy[i] = y; sz[i] = z;
            sw[i] = fmaf(x, x, fmaf(y, y, z * z));
        }
    }
    __syncthreads();

    const float* qp = qk + (size_t)b * 3 * NPTS;
    int      m[RPT];
    float    a0x[RPT], a0y[RPT], a0z[RPT], sqa[RPT];
    uint64_t ax2[RPT], ay2[RPT], az2[RPT];
    float    best[RPT];
    int      bg[RPT];

    #pragma unroll
    for (int r = 0; r < RPT; r++) {
        m[r] = blockIdx.x * ROWS_PER_BLOCK + r * THREADS + threadIdx.x;
        float x = qp[m[r]];
        float y = qp[NPTS + m[r]];
        float z = qp[2 * NPTS + m[r]];
        a0x[r] = -2.0f * x;  a0y[r] = -2.0f * y;  a0z[r] = -2.0f * z;
        ax2[r] = pack2(a0x[r], a0x[r]);
        ay2[r] = pack2(a0y[r], a0y[r]);
        az2[r] = pack2(a0z[r], a0z[r]);
        sqa[r] = fmaf(x, x, fmaf(y, y, z * z));
        best[r] = __int_as_float(0x7f800000);   // +inf
        bg[r] = 0;
    }

    const float INF = __int_as_float(0x7f800000);

    // Main loop: v = ||p||^2 - 2 a.p  (same argmin as d^2). Packed FMA chain,
    // 4 independent scalar FMNMX accumulator chains per row. Index recovered
    // by replaying the winning 64-element group afterwards.
    for (int g = 0; g < NGROUPS; g++) {
        float gla[RPT], gha[RPT], glb[RPT], ghb[RPT];
        #pragma unroll
        for (int r = 0; r < RPT; r++) {
            gla[r] = INF; gha[r] = INF; glb[r] = INF; ghb[r] = INF;
        }

        const int base = g * GSIZE;
        #pragma unroll 2
        for (int k = 0; k < GSIZE; k += 4) {
            const int n = base + k;
            ulonglong2 X = *(const ulonglong2*)(sx + n);  // (x[n],x[n+1]),(x[n+2],x[n+3])
            ulonglong2 Y = *(const ulonglong2*)(sy + n);
            ulonglong2 Z = *(const ulonglong2*)(sz + n);
            ulonglong2 W = *(const ulonglong2*)(sw + n);
            #pragma unroll
            for (int r = 0; r < RPT; r++) {
                float l0, h0, l1, h1;
                fma2_last(l0, h0, ax2[r], X.x,
                          fma2(ay2[r], Y.x, fma2(az2[r], Z.x, W.x)));
                fma2_last(l1, h1, ax2[r], X.y,
                          fma2(ay2[r], Y.y, fma2(az2[r], Z.y, W.y)));
                gla[r] = fminf(gla[r], l0);
                gha[r] = fminf(gha[r], h0);
                glb[r] = fminf(glb[r], l1);
                ghb[r] = fminf(ghb[r], h1);
            }
        }
        #pragma unroll
        for (int r = 0; r < RPT; r++) {
            float gm = fminf(fminf(gla[r], gha[r]), fminf(glb[r], ghb[r]));
            bg[r]   = (gm < best[r]) ? g : bg[r];   // strict < keeps earliest group
            best[r] = fminf(best[r], gm);
        }
    }

    // Replay winning group per row: first-argmin within it (exact same FMA chain).
    float acc = 0.0f;
    #pragma unroll
    for (int r = 0; r < RPT; r++) {
        const int base = bg[r] * GSIZE;
        float lb = INF;
        int   bi = base;
        for (int k = 0; k < GSIZE; k++) {
            const int n = base + k;
            float v = fmaf(a0x[r], sx[n], fmaf(a0y[r], sy[n], fmaf(a0z[r], sz[n], sw[n])));
            bi = (v < lb) ? n : bi;                 // strict < keeps first index
            lb = fminf(lb, v);
        }
        float d2   = best[r] + sqa[r];
        float mind = sqrtf(fmaxf(d2, EPSF));
        float sg   = 0.5f * (qs[(size_t)b * NPTS + m[r]] + ts[(size_t)b * NPTS + bi]);
        acc += logf(sg) + mind / sg;
    }

    // Block reduction -> per-block partial.
    __shared__ float red[THREADS];
    red[threadIdx.x] = acc;
    __syncthreads();
    #pragma unroll
    for (int s = THREADS / 2; s > 32; s >>= 1) {
        if (threadIdx.x < s) red[threadIdx.x] += red[threadIdx.x + s];
        __syncthreads();
    }
    if (threadIdx.x < 32) {
        float v = red[threadIdx.x] + red[threadIdx.x + 32];
        #pragma unroll
        for (int o = 16; o > 0; o >>= 1)
            v += __shfl_down_sync(0xffffffffu, v, o);
        if (threadIdx.x == 0) {
            int bid = blockIdx.z * (BBATCH * TILES) + blockIdx.y * TILES + blockIdx.x;
            g_partials[bid] = v;
        }
    }
}

__global__ __launch_bounds__(NBLOCKS)
void chamfer_final_kernel(float* __restrict__ out)
{
    __shared__ double red[NBLOCKS];
    red[threadIdx.x] = (double)g_partials[threadIdx.x];
    __syncthreads();
    for (int s = NBLOCKS / 2; s > 0; s >>= 1) {
        if (threadIdx.x < s) red[threadIdx.x] += red[threadIdx.x + s];
        __syncthreads();
    }
    if (threadIdx.x == 0)
        out[0] = (float)(red[0] * (1.0 / ((double)BBATCH * (double)NPTS)));
}

extern "C" void kernel_launch(void* const* d_in, const int* in_sizes, int n_in,
                              void* d_out, int out_size)
{
    (void)in_sizes; (void)n_in; (void)out_size;
    const float* kp1  = (const float*)d_in[0];  // [B, 3, M]
    const float* kp2  = (const float*)d_in[1];  // [B, 3, N]
    const float* sig1 = (const float*)d_in[2];  // [B, M]
    const float* sig2 = (const float*)d_in[3];  // [B, N]
    float* out = (float*)d_out;

    cudaFuncSetAttribute(chamfer_dir_kernel,
                         cudaFuncAttributeMaxDynamicSharedMemorySize, 65536);

    dim3 grid(TILES, BBATCH, 2);
    chamfer_dir_kernel<<<grid, THREADS, 65536>>>(kp1, kp2, sig1, sig2);
    chamfer_final_kernel<<<1, NBLOCKS>>>(out);
}

// round 5
// speedup vs baseline: 1.2843x; 1.0473x over previous
#include <cuda_runtime.h>
#include <math.h>
#include <stdint.h>

#define BBATCH 16
#define NPTS   4096
#define THREADS 512
#define RPT 2
#define ROWS_PER_BLOCK (THREADS * RPT)     // 1024
#define TILES (NPTS / ROWS_PER_BLOCK)      // 4
#define NBLOCKS (TILES * BBATCH * 2)       // 128  -> one block per SM, single wave
#define GSIZE 64
#define NGROUPS (NPTS / GSIZE)             // 64
#define EPSF 1e-12f

__device__ float g_partials[NBLOCKS];
__device__ unsigned int g_done = 0;

__device__ __forceinline__ uint64_t pack2(float lo, float hi) {
    uint64_t r;
    asm("mov.b64 %0, {%1,%2};" : "=l"(r) : "f"(lo), "f"(hi));
    return r;
}
// Packed 2xfp32 FMA, result stays in b64 domain (register pair).
__device__ __forceinline__ uint64_t fma2(uint64_t a, uint64_t b, uint64_t c) {
    uint64_t d;
    asm("fma.rn.f32x2 %0, %1, %2, %3;" : "=l"(d) : "l"(a), "l"(b), "l"(c));
    return d;
}
// Final packed FMA of a chain: destination pair aliased to two scalar floats.
__device__ __forceinline__ void fma2_last(float& lo, float& hi,
                                          uint64_t a, uint64_t b, uint64_t c) {
    asm("{\n\t.reg .b64 t;\n\tfma.rn.f32x2 t, %2, %3, %4;\n\tmov.b64 {%0,%1}, t;\n\t}"
        : "=f"(lo), "=f"(hi) : "l"(a), "l"(b), "l"(c));
}

// One direction per blockIdx.z:
//   z==0: queries = keypoints1 (forward),  targets = keypoints2
//   z==1: queries = keypoints2 (backward), targets = keypoints1
__global__ __launch_bounds__(THREADS)
void chamfer_fused_kernel(const float* __restrict__ kp1,
                          const float* __restrict__ kp2,
                          const float* __restrict__ sig1,
                          const float* __restrict__ sig2,
                          float* __restrict__ out)
{
    const float *qk, *tk, *qs, *ts;
    if (blockIdx.z == 0) { qk = kp1; tk = kp2; qs = sig1; ts = sig2; }
    else                 { qk = kp2; tk = kp1; qs = sig2; ts = sig1; }

    const int b = blockIdx.y;

    // SoA target tile: x, y, z, ||p||^2 — packed pairs come free from LDS.128
    extern __shared__ float sm[];
    float* sx = sm;
    float* sy = sm + NPTS;
    float* sz = sm + 2 * NPTS;
    float* sw = sm + 3 * NPTS;

    {
        const float* tp = tk + (size_t)b * 3 * NPTS;
        for (int i = threadIdx.x; i < NPTS; i += THREADS) {
            float x = tp[i];
            float y = tp[NPTS + i];
            float z = tp[2 * NPTS + i];
            sx[i] = x; sy[i] = y; sz[i] = z;
            sw[i] = fmaf(x, x, fmaf(y, y, z * z));
        }
    }
    __syncthreads();

    const float* qp = qk + (size_t)b * 3 * NPTS;
    int      m[RPT];
    float    a0x[RPT], a0y[RPT], a0z[RPT], sqa[RPT];
    uint64_t ax2[RPT], ay2[RPT], az2[RPT];
    float    best[RPT];
    int      bg[RPT];

    #pragma unroll
    for (int r = 0; r < RPT; r++) {
        m[r] = blockIdx.x * ROWS_PER_BLOCK + r * THREADS + threadIdx.x;
        float x = qp[m[r]];
        float y = qp[NPTS + m[r]];
        float z = qp[2 * NPTS + m[r]];
        a0x[r] = -2.0f * x;  a0y[r] = -2.0f * y;  a0z[r] = -2.0f * z;
        ax2[r] = pack2(a0x[r], a0x[r]);
        ay2[r] = pack2(a0y[r], a0y[r]);
        az2[r] = pack2(a0z[r], a0z[r]);
        sqa[r] = fmaf(x, x, fmaf(y, y, z * z));
        best[r] = __int_as_float(0x7f800000);   // +inf
        bg[r] = 0;
    }

    const float INF = __int_as_float(0x7f800000);

    // Main loop: v = ||p||^2 - 2 a.p  (same argmin as d^2). Packed FMA chain,
    // 4 independent scalar FMNMX accumulator chains per row. Index recovered
    // by replaying the winning 64-element group afterwards.
    for (int g = 0; g < NGROUPS; g++) {
        float gla[RPT], gha[RPT], glb[RPT], ghb[RPT];
        #pragma unroll
        for (int r = 0; r < RPT; r++) {
            gla[r] = INF; gha[r] = INF; glb[r] = INF; ghb[r] = INF;
        }

        const int base = g * GSIZE;
        #pragma unroll 2
        for (int k = 0; k < GSIZE; k += 4) {
            const int n = base + k;
            ulonglong2 X = *(const ulonglong2*)(sx + n);  // (x[n],x[n+1]),(x[n+2],x[n+3])
            ulonglong2 Y = *(const ulonglong2*)(sy + n);
            ulonglong2 Z = *(const ulonglong2*)(sz + n);
            ulonglong2 W = *(const ulonglong2*)(sw + n);
            #pragma unroll
            for (int r = 0; r < RPT; r++) {
                float l0, h0, l1, h1;
                fma2_last(l0, h0, ax2[r], X.x,
                          fma2(ay2[r], Y.x, fma2(az2[r], Z.x, W.x)));
                fma2_last(l1, h1, ax2[r], X.y,
                          fma2(ay2[r], Y.y, fma2(az2[r], Z.y, W.y)));
                gla[r] = fminf(gla[r], l0);
                gha[r] = fminf(gha[r], h0);
                glb[r] = fminf(glb[r], l1);
                ghb[r] = fminf(ghb[r], h1);
            }
        }
        #pragma unroll
        for (int r = 0; r < RPT; r++) {
            float gm = fminf(fminf(gla[r], gha[r]), fminf(glb[r], ghb[r]));
            bg[r]   = (gm < best[r]) ? g : bg[r];   // strict < keeps earliest group
            best[r] = fminf(best[r], gm);
        }
    }

    // Replay winning group per row: first-argmin within it (exact same FMA chain).
    float acc = 0.0f;
    #pragma unroll
    for (int r = 0; r < RPT; r++) {
        const int base = bg[r] * GSIZE;
        float lb = INF;
        int   bi = base;
        for (int k = 0; k < GSIZE; k++) {
            const int n = base + k;
            float v = fmaf(a0x[r], sx[n], fmaf(a0y[r], sy[n], fmaf(a0z[r], sz[n], sw[n])));
            bi = (v < lb) ? n : bi;                 // strict < keeps first index
            lb = fminf(lb, v);
        }
        float d2   = best[r] + sqa[r];
        float mind = sqrtf(fmaxf(d2, EPSF));
        float sg   = 0.5f * (qs[(size_t)b * NPTS + m[r]] + ts[(size_t)b * NPTS + bi]);
        acc += logf(sg) + mind / sg;
    }

    // Block reduction -> per-block partial.
    __shared__ float red[THREADS];
    __shared__ int   s_last;
    red[threadIdx.x] = acc;
    __syncthreads();
    #pragma unroll
    for (int s = THREADS / 2; s > 32; s >>= 1) {
        if (threadIdx.x < s) red[threadIdx.x] += red[threadIdx.x + s];
        __syncthreads();
    }
    if (threadIdx.x < 32) {
        float v = red[threadIdx.x] + red[threadIdx.x + 32];
        #pragma unroll
        for (int o = 16; o > 0; o >>= 1)
            v += __shfl_down_sync(0xffffffffu, v, o);
        if (threadIdx.x == 0) {
            int bid = blockIdx.z * (BBATCH * TILES) + blockIdx.y * TILES + blockIdx.x;
            g_partials[bid] = v;
            __threadfence();
            unsigned int old = atomicAdd(&g_done, 1u);
            s_last = (old == NBLOCKS - 1);
        }
    }
    __syncthreads();

    // Last block to finish folds the 128 partials (deterministic fixed-order
    // tree) and resets the done-counter for the next graph replay.
    if (s_last) {
        __shared__ double dred[NBLOCKS];
        if (threadIdx.x < NBLOCKS) {
            float p;
            asm volatile("ld.global.cg.f32 %0, [%1];"
                         : "=f"(p) : "l"(g_partials + threadIdx.x));
            dred[threadIdx.x] = (double)p;
        }
        __syncthreads();
        for (int s = NBLOCKS / 2; s > 0; s >>= 1) {
            if (threadIdx.x < s) dred[threadIdx.x] += dred[threadIdx.x + s];
            __syncthreads();
        }
        if (threadIdx.x == 0) {
            out[0] = (float)(dred[0] * (1.0 / ((double)BBATCH * (double)NPTS)));
            g_done = 0;   // reset for next replay
        }
    }
}

extern "C" void kernel_launch(void* const* d_in, const int* in_sizes, int n_in,
                              void* d_out, int out_size)
{
    (void)in_sizes; (void)n_in; (void)out_size;
    const float* kp1  = (const float*)d_in[0];  // [B, 3, M]
    const float* kp2  = (const float*)d_in[1];  // [B, 3, N]
    const float* sig1 = (const float*)d_in[2];  // [B, M]
    const float* sig2 = (const float*)d_in[3];  // [B, N]
    float* out = (float*)d_out;

    cudaFuncSetAttribute(chamfer_fused_kernel,
                         cudaFuncAttributeMaxDynamicSharedMemorySize, 65536);

    dim3 grid(TILES, BBATCH, 2);
    chamfer_fused_kernel<<<grid, THREADS, 65536>>>(kp1, kp2, sig1, sig2, out);
}